// round 16
// baseline (speedup 1.0000x reference)
#include <cuda_runtime.h>

#define NN 50000
#define EE 1600000
#define H  64
#define STEAL (EE/32)   // 50000 steal units of 32 edges (2 x 16-edge subtiles)

typedef unsigned long long ull;

// ---------------- scratch (device globals; no allocation allowed) ----------------
__device__ float g_h[NN*H];
__device__ float g_A[NN*H];      // h@Wa + e_b1
__device__ float g_B[NN*H];      // h@Wb
__device__ float g_magg[NN*H];   // segment-summed messages
__device__ float g_cagg4[NN*4];  // segment-summed coord updates (padded)
__device__ float g_vel[NN];      // vel_scale
__device__ float g_deg[NN];      // clipped out-degree (float)
__device__ int   g_cnt[NN];      // raw out-degree
__device__ int   g_off[NN];      // fill cursors
__device__ float g_x4[NN*4];     // padded coords
__device__ float g_v4[NN*4];     // padded velocities
__device__ int   g_tile;         // dynamic steal cursor
// r-sorted edge arrays
__device__ int    g_er[EE];
__device__ int    g_ec[EE];
__device__ float2 g_ea2[EE];

__device__ __forceinline__ float silu_f(float x){
    float th;
    asm("tanh.approx.f32 %0, %1;" : "=f"(th) : "f"(0.5f*x));
    return 0.5f*x*th + 0.5f*x;
}
__device__ __forceinline__ ull pack2(float x, float y){
    ull r; asm("mov.b64 %0, {%1,%2};" : "=l"(r) : "f"(x), "f"(y)); return r;
}
__device__ __forceinline__ float2 unpack2(ull p){
    float2 r; asm("mov.b64 {%0,%1}, %2;" : "=f"(r.x), "=f"(r.y) : "l"(p)); return r;
}
__device__ __forceinline__ void fma2(ull& d, ull a, ull b){
    asm("fma.rn.f32x2 %0, %1, %2, %0;" : "+l"(d) : "l"(a), "l"(b));
}
__device__ __forceinline__ void red4(float* p, float a, float b, float c, float d){
    asm volatile("red.global.add.v4.f32 [%0], {%1,%2,%3,%4};"
                 :: "l"(p), "f"(a), "f"(b), "f"(c), "f"(d) : "memory");
}
__device__ __forceinline__ void red2(float* p, float a, float b){
    asm volatile("red.global.add.v2.f32 [%0], {%1,%2};"
                 :: "l"(p), "f"(a), "f"(b) : "memory");
}
__device__ __forceinline__ unsigned to_tf32(float f){
    unsigned r; asm("cvt.rna.tf32.f32 %0, %1;" : "=r"(r) : "f"(f)); return r;
}
__device__ __forceinline__ void split_tf32(float f, unsigned& hi, unsigned& lo){
    hi = to_tf32(f);
    lo = to_tf32(f - __uint_as_float(hi));
}
__device__ __forceinline__ void pf_l1(const float* p){
    asm volatile("prefetch.global.L1 [%0];" :: "l"(p));
}
// m16n8k8 tf32 MMA: D += A@B (A row-major 16x8, B col-major 8x8, fp32 accum)
__device__ __forceinline__ void mma8(float& d0, float& d1, float& d2, float& d3,
                                     unsigned a0, unsigned a1, unsigned a2, unsigned a3,
                                     ull b01){
    unsigned b0 = (unsigned)b01, b1 = (unsigned)(b01 >> 32);
    asm("mma.sync.aligned.m16n8k8.row.col.f32.tf32.tf32.f32 "
        "{%0,%1,%2,%3}, {%4,%5,%6,%7}, {%8,%9}, {%0,%1,%2,%3};"
        : "+f"(d0), "+f"(d1), "+f"(d2), "+f"(d3)
        : "r"(a0), "r"(a1), "r"(a2), "r"(a3), "r"(b0), "r"(b1));
}

// ---------------- init ------------------------------------------------------------
__global__ void k_init(const float* __restrict__ his, const float* __restrict__ emb_w,
                       const float* __restrict__ emb_b, const float* __restrict__ x,
                       const float* __restrict__ v){
    int idx = blockIdx.x*blockDim.x + threadIdx.x;
    if (idx < NN*H){
        int n = idx >> 6, j = idx & 63;
        float acc = emb_b[j];
        #pragma unroll
        for (int k=0;k<16;k++) acc += his[n*16+k]*emb_w[k*H+j];
        g_h[idx] = acc;
    }
    if (idx < NN){
        g_x4[idx*4+0]=x[idx*3+0]; g_x4[idx*4+1]=x[idx*3+1]; g_x4[idx*4+2]=x[idx*3+2]; g_x4[idx*4+3]=0.f;
        g_v4[idx*4+0]=v[idx*3+0]; g_v4[idx*4+1]=v[idx*3+1]; g_v4[idx*4+2]=v[idx*3+2]; g_v4[idx*4+3]=0.f;
        g_cnt[idx] = 0;
    }
}

__global__ void k_deg(const int* __restrict__ edges){
    int e = blockIdx.x*blockDim.x + threadIdx.x;
    if (e < EE) atomicAdd(&g_cnt[edges[e]], 1);
}

// single-block exclusive scan over g_cnt -> g_off; also g_deg = max(cnt,1)
__global__ void k_scan(){
    __shared__ int s_part[1024];
    int tid = threadIdx.x;
    const int CH = (NN + 1023)/1024;
    int base = tid*CH;
    int sum = 0;
    #pragma unroll 7
    for (int i=0;i<CH;i++){ int n=base+i; if(n<NN) sum += g_cnt[n]; }
    s_part[tid] = sum;
    __syncthreads();
    for (int off=1; off<1024; off<<=1){
        int t = (tid >= off) ? s_part[tid-off] : 0;
        __syncthreads();
        s_part[tid] += t;
        __syncthreads();
    }
    int run = s_part[tid] - sum;
    for (int i=0;i<CH;i++){
        int n = base+i;
        if (n < NN){
            int c = g_cnt[n];
            g_off[n] = run;
            g_deg[n] = (c > 0) ? (float)c : 1.0f;
            run += c;
        }
    }
}

__global__ void k_fill(const int* __restrict__ edges, const float* __restrict__ edge_attr){
    int e = blockIdx.x*blockDim.x + threadIdx.x;
    if (e < EE){
        int r = edges[e];
        int pos = atomicAdd(&g_off[r], 1);
        g_er[pos] = r;
        g_ec[pos] = edges[EE+e];
        g_ea2[pos] = ((const float2*)edge_attr)[e];
    }
}

// ------ per-layer node precompute (f32x2): A,B, vel_scale; zero aggs; reset cursor
__global__ void k_prevel(const float* __restrict__ e_w1, const float* __restrict__ e_b1,
                         const float* __restrict__ v_w1, const float* __restrict__ v_b1,
                         const float* __restrict__ v_w2, const float* __restrict__ v_b2){
    extern __shared__ float sp[];
    float* s_ew  = sp;
    float* s_vw  = sp + 8192;
    float* s_eb1 = sp + 12288;
    float* s_vb1 = sp + 12352;
    float* s_vw2 = sp + 12416;
    int tid = threadIdx.x;
    if (blockIdx.x == 0 && tid == 0) g_tile = 0;
    for (int i=tid; i<8192; i+=blockDim.x) s_ew[i] = e_w1[i];
    for (int i=tid; i<4096; i+=blockDim.x) s_vw[i] = v_w1[i];
    if (tid < 64){ s_eb1[tid]=e_b1[tid]; s_vb1[tid]=v_b1[tid]; s_vw2[tid]=v_w2[tid]; }
    __syncthreads();
    int lane = tid & 31, warp = tid >> 5;
    int j0 = 2*lane;
    int wpb = blockDim.x >> 5;
    float vb2 = v_b2[0];
    for (int n = blockIdx.x*wpb + warp; n < NN; n += gridDim.x*wpb){
        float h0 = g_h[n*H+j0], h1 = g_h[n*H+j0+1];
        ull a01 = *(const ull*)&s_eb1[j0];
        ull b01 = pack2(0.f, 0.f);
        ull t01 = *(const ull*)&s_vb1[j0];
        #pragma unroll
        for (int k=0;k<H;k++){
            float hk = __shfl_sync(0xffffffffu, (k&1)?h1:h0, k>>1);
            ull hk2 = pack2(hk, hk);
            fma2(a01, hk2, *(const ull*)&s_ew[k*H+j0]);
            fma2(b01, hk2, *(const ull*)&s_ew[(H+k)*H+j0]);
            fma2(t01, hk2, *(const ull*)&s_vw[k*H+j0]);
        }
        *(ull*)&g_A[n*H+j0] = a01;
        *(ull*)&g_B[n*H+j0] = b01;
        *(float2*)&g_magg[n*H+j0] = make_float2(0.f,0.f);
        float2 tv = unpack2(t01);
        float p = silu_f(tv.x)*s_vw2[j0] + silu_f(tv.y)*s_vw2[j0+1];
        #pragma unroll
        for (int o=16;o>0;o>>=1) p += __shfl_xor_sync(0xffffffffu, p, o);
        if (lane == 0){
            g_vel[n] = p + vb2;
            *(float4*)&g_cagg4[n*4] = make_float4(0.f,0.f,0.f,0.f);
        }
    }
}

// ------- edge kernel: 16-edge warp subtiles, 2-term tf32 mma (A-split), prefetch --
__global__ void __launch_bounds__(256, 3)
k_edge(const float* __restrict__ e_w1, const float* __restrict__ e_w2,
       const float* __restrict__ e_b2, const float* __restrict__ c_w1,
       const float* __restrict__ c_b1, const float* __restrict__ c_w2){
    extern __shared__ float sm[];
    ull*   w2p   = (ull*)sm;         // 2048 ull (packed tf32 B frags, GEMM1)
    ull*   c1p   = (ull*)(sm + 4096);// 2048 ull (GEMM2)
    float* s_wr  = sm + 8192;        // 64
    float* s_we0 = sm + 8256;
    float* s_we1 = sm + 8320;
    float* s_eb2 = sm + 8384;
    float* s_cb1 = sm + 8448;
    float* s_cw2 = sm + 8512;        // .. 8576
    int tid  = threadIdx.x;
    int wid  = tid >> 5, lane = tid & 31;
    float* wbp  = sm + 8576 + wid*1088;   // per-warp region (1088 floats)
    float* s_t  = wbp;                    // 64 x 16  (full fp32)
    int*   s_r  = (int*)(wbp + 1024);     // 16
    float* s_dx = wbp + 1040;             // 16
    float* s_dy = wbp + 1056;
    float* s_dz = wbp + 1072;
    // total smem: 8576 + 8*1088 = 17280 floats = 69120 B

    // pack weights into per-(ktile,ntile) lane-ordered tf32 B fragments
    for (int idx=tid; idx<2048; idx+=256){
        int tile = idx >> 5, vl = idx & 31;
        int kt = tile >> 3, nt = tile & 7;
        int tg = vl & 3,  gd = vl >> 2;
        int k0 = kt*8 + tg, j = nt*8 + gd;
        unsigned b0 = to_tf32(e_w2[k0*64 + j]);
        unsigned b1 = to_tf32(e_w2[(k0+4)*64 + j]);
        w2p[idx] = ((ull)b1 << 32) | (ull)b0;
        b0 = to_tf32(c_w1[k0*64 + j]);
        b1 = to_tf32(c_w1[(k0+4)*64 + j]);
        c1p[idx] = ((ull)b1 << 32) | (ull)b0;
    }
    if (tid < 64){
        s_wr [tid] = e_w1[128*H+tid];
        s_we0[tid] = e_w1[129*H+tid];
        s_we1[tid] = e_w1[130*H+tid];
        s_eb2[tid] = e_b2[tid];
        s_cb1[tid] = c_b1[tid];
        s_cw2[tid] = c_w2[tid];
    }
    __syncthreads();

    const unsigned FM = 0xffffffffu;
    int el = lane & 15, hf = lane >> 4;   // P1: 2 lanes/edge
    int tig = lane & 3, gid = lane >> 2;  // mma fragment coords

    int base = 0;
    if (lane == 0) base = atomicAdd(&g_tile, 1);
    base = __shfl_sync(FM, base, 0);

    while (base < STEAL){
        #pragma unroll 1
        for (int sub=0; sub<2; sub++){
            // ---- P1: gather + first-layer pre + silu -> fp32 s_t[k][e] ----
            {
                int e = base*32 + sub*16 + el;
                int r = g_er[e], c = g_ec[e];
                if (sub == 0){
                    // prefetch next subtile's rows during this gather window
                    int e2 = e + 16;
                    int rn = g_er[e2], cn = g_ec[e2];
                    pf_l1(g_A + rn*H + hf*32);
                    pf_l1(g_B + cn*H + hf*32);
                }
                float4 xr = *(const float4*)&g_x4[r*4];
                float4 xc = *(const float4*)&g_x4[c*4];
                float dx = xr.x-xc.x, dy = xr.y-xc.y, dz = xr.z-xc.z;
                float radial = dx*dx + dy*dy + dz*dz;
                float2 ea = g_ea2[e];
                const float4* Ap = (const float4*)(g_A + r*H + hf*32);
                const float4* Bp = (const float4*)(g_B + c*H + hf*32);
                int kb = hf*32;
                #pragma unroll
                for (int q=0;q<8;q++){
                    float4 av = Ap[q], bv = Bp[q];
                    int k = kb + 4*q;
                    float4 w1 = *(const float4*)&s_wr [k];
                    float4 w2 = *(const float4*)&s_we0[k];
                    float4 w3 = *(const float4*)&s_we1[k];
                    s_t[(k+0)*16+el] = silu_f(av.x + bv.x + radial*w1.x + ea.x*w2.x + ea.y*w3.x);
                    s_t[(k+1)*16+el] = silu_f(av.y + bv.y + radial*w1.y + ea.x*w2.y + ea.y*w3.y);
                    s_t[(k+2)*16+el] = silu_f(av.z + bv.z + radial*w1.z + ea.x*w2.z + ea.y*w3.z);
                    s_t[(k+3)*16+el] = silu_f(av.w + bv.w + radial*w1.w + ea.x*w2.w + ea.y*w3.w);
                }
                if (!hf){ s_r[el]=r; s_dx[el]=dx; s_dy[el]=dy; s_dz[el]=dz; }
            }
            __syncwarp();

            int r0 = s_r[gid], r1 = s_r[gid+8];

            // ---- GEMM1 (kt-outer, A-split 2-term): M = t @ e_w2 + b ----
            float d[32];
            #pragma unroll
            for (int nt=0;nt<8;nt++){
                int c0 = nt*8 + 2*tig;
                d[nt*4+0] = s_eb2[c0];   d[nt*4+1] = s_eb2[c0+1];
                d[nt*4+2] = d[nt*4+0];   d[nt*4+3] = d[nt*4+1];
            }
            #pragma unroll
            for (int kt=0;kt<8;kt++){
                const float* bp = s_t + (kt*8 + tig)*16 + gid;
                unsigned h0,h1,h2,h3, l0,l1,l2,l3;
                split_tf32(bp[0],  h0, l0);
                split_tf32(bp[8],  h1, l1);
                split_tf32(bp[64], h2, l2);
                split_tf32(bp[72], h3, l3);
                #pragma unroll
                for (int nt=0;nt<8;nt++){
                    ull b01 = w2p[(kt*8+nt)*32 + lane];
                    mma8(d[nt*4],d[nt*4+1],d[nt*4+2],d[nt*4+3], h0,h1,h2,h3, b01);
                    mma8(d[nt*4],d[nt*4+1],d[nt*4+2],d[nt*4+3], l0,l1,l2,l3, b01);
                }
            }
            // epilogue: silu, scatter m_agg, store fp32 m -> s_t
            #pragma unroll
            for (int nt=0;nt<8;nt++){
                int c0 = nt*8 + 2*tig;
                float m0 = silu_f(d[nt*4+0]), m1 = silu_f(d[nt*4+1]);
                float m2 = silu_f(d[nt*4+2]), m3 = silu_f(d[nt*4+3]);
                red2(&g_magg[r0*H + c0], m0, m1);
                red2(&g_magg[r1*H + c0], m2, m3);
                s_t[ c0   *16 + gid  ] = m0;
                s_t[(c0+1)*16 + gid  ] = m1;
                s_t[ c0   *16 + gid+8] = m2;
                s_t[(c0+1)*16 + gid+8] = m3;
            }
            __syncwarp();

            // ---- GEMM2 (kt-outer, A-split): U = m @ c_w1 + cb1; g = sum silu*cw2 -
            #pragma unroll
            for (int nt=0;nt<8;nt++){
                int c0 = nt*8 + 2*tig;
                d[nt*4+0] = s_cb1[c0];   d[nt*4+1] = s_cb1[c0+1];
                d[nt*4+2] = d[nt*4+0];   d[nt*4+3] = d[nt*4+1];
            }
            #pragma unroll
            for (int kt=0;kt<8;kt++){
                const float* bp = s_t + (kt*8 + tig)*16 + gid;
                unsigned h0,h1,h2,h3, l0,l1,l2,l3;
                split_tf32(bp[0],  h0, l0);
                split_tf32(bp[8],  h1, l1);
                split_tf32(bp[64], h2, l2);
                split_tf32(bp[72], h3, l3);
                #pragma unroll
                for (int nt=0;nt<8;nt++){
                    ull b01 = c1p[(kt*8+nt)*32 + lane];
                    mma8(d[nt*4],d[nt*4+1],d[nt*4+2],d[nt*4+3], h0,h1,h2,h3, b01);
                    mma8(d[nt*4],d[nt*4+1],d[nt*4+2],d[nt*4+3], l0,l1,l2,l3, b01);
                }
            }
            float gp0 = 0.f, gp1 = 0.f;
            #pragma unroll
            for (int nt=0;nt<8;nt++){
                int c0 = nt*8 + 2*tig;
                float w0 = s_cw2[c0], w1 = s_cw2[c0+1];
                gp0 += silu_f(d[nt*4+0])*w0 + silu_f(d[nt*4+1])*w1;
                gp1 += silu_f(d[nt*4+2])*w0 + silu_f(d[nt*4+3])*w1;
            }
            gp0 += __shfl_xor_sync(FM, gp0, 1);
            gp0 += __shfl_xor_sync(FM, gp0, 2);
            gp1 += __shfl_xor_sync(FM, gp1, 1);
            gp1 += __shfl_xor_sync(FM, gp1, 2);
            if (tig == 0){
                float cx0 = s_dx[gid]*gp0,   cy0 = s_dy[gid]*gp0,   cz0 = s_dz[gid]*gp0;
                float cx1 = s_dx[gid+8]*gp1, cy1 = s_dy[gid+8]*gp1, cz1 = s_dz[gid+8]*gp1;
                if (r0 == r1){
                    red4(&g_cagg4[r0*4], cx0+cx1, cy0+cy1, cz0+cz1, 0.f);
                } else {
                    red4(&g_cagg4[r0*4], cx0, cy0, cz0, 0.f);
                    red4(&g_cagg4[r1*4], cx1, cy1, cz1, 0.f);
                }
            }
            __syncwarp();   // protect s_t/s_r before next subtile's P1
        }
        if (lane == 0) base = atomicAdd(&g_tile, 1);
        base = __shfl_sync(FM, base, 0);
    }
}

// -------- fused node MLP + state update (f32x2); last layer writes output ---------
__global__ void k_node(const float* __restrict__ n_w1, const float* __restrict__ n_b1,
                       const float* __restrict__ n_w2, const float* __restrict__ n_b2,
                       float* __restrict__ out, int last){
    extern __shared__ float sn[];
    float* s_w1 = sn;
    float* s_w2 = sn + 8192;
    float* s_b1 = sn + 12288;
    float* s_b2 = sn + 12352;
    int tid = threadIdx.x;
    for (int i=tid; i<8192; i+=blockDim.x) s_w1[i] = n_w1[i];
    for (int i=tid; i<4096; i+=blockDim.x) s_w2[i] = n_w2[i];
    if (tid < 64){ s_b1[tid]=n_b1[tid]; s_b2[tid]=n_b2[tid]; }
    __syncthreads();
    int lane = tid & 31, warp = tid >> 5;
    int j0 = 2*lane;
    int wpb = blockDim.x >> 5;
    for (int n = blockIdx.x*wpb + warp; n < NN; n += gridDim.x*wpb){
        float h0 = g_h[n*H+j0],    h1 = g_h[n*H+j0+1];
        float m0 = g_magg[n*H+j0], m1 = g_magg[n*H+j0+1];
        ull u01 = *(const ull*)&s_b1[j0];
        #pragma unroll
        for (int k=0;k<H;k++){
            float hk = __shfl_sync(0xffffffffu, (k&1)?h1:h0, k>>1);
            float mk = __shfl_sync(0xffffffffu, (k&1)?m1:m0, k>>1);
            fma2(u01, pack2(hk,hk), *(const ull*)&s_w1[k*H+j0]);
            fma2(u01, pack2(mk,mk), *(const ull*)&s_w1[(H+k)*H+j0]);
        }
        float2 uv = unpack2(u01);
        float u0 = silu_f(uv.x), u1 = silu_f(uv.y);
        ull a01 = *(const ull*)&s_b2[j0];
        #pragma unroll
        for (int k=0;k<H;k++){
            float uk = __shfl_sync(0xffffffffu, (k&1)?u1:u0, k>>1);
            fma2(a01, pack2(uk,uk), *(const ull*)&s_w2[k*H+j0]);
        }
        float2 av = unpack2(a01);
        float hn0 = 2.f*h0 + av.x, hn1 = 2.f*h1 + av.y;
        *(float2*)&g_h[n*H+j0] = make_float2(hn0, hn1);
        float vn = 0.f, xn = 0.f;
        if (lane < 3){
            float dg = g_deg[n];
            float cm = g_cagg4[n*4+lane] / dg;
            float vi = g_v4[n*4+lane];
            vn = vi + cm + g_vel[n]*vi;
            g_v4[n*4+lane] = vn;
            xn = g_x4[n*4+lane] + vn;
            g_x4[n*4+lane] = xn;
        }
        if (last){
            *(float2*)&out[NN*3 + n*H + j0] = make_float2(hn0, hn1);
            if (lane < 3){
                out[n*3 + lane] = xn;
                out[NN*3 + NN*H + n*3 + lane] = vn;
            }
        }
    }
}

extern "C" void kernel_launch(void* const* d_in, const int* in_sizes, int n_in,
                              void* d_out, int out_size){
    const float* his  = (const float*)d_in[0];
    const float* x    = (const float*)d_in[1];
    const float* v    = (const float*)d_in[2];
    const float* edge_attr = (const float*)d_in[3];
    const int*   edges= (const int*)  d_in[4];
    const float* emb_w= (const float*)d_in[5];
    const float* emb_b= (const float*)d_in[6];
    const float* e_w1 = (const float*)d_in[7];
    const float* e_b1 = (const float*)d_in[8];
    const float* e_w2 = (const float*)d_in[9];
    const float* e_b2 = (const float*)d_in[10];
    const float* c_w1 = (const float*)d_in[11];
    const float* c_b1 = (const float*)d_in[12];
    const float* c_w2 = (const float*)d_in[13];
    const float* n_w1 = (const float*)d_in[14];
    const float* n_b1 = (const float*)d_in[15];
    const float* n_w2 = (const float*)d_in[16];
    const float* n_b2 = (const float*)d_in[17];
    const float* v_w1 = (const float*)d_in[18];
    const float* v_b1 = (const float*)d_in[19];
    const float* v_w2 = (const float*)d_in[20];
    const float* v_b2 = (const float*)d_in[21];

    const int PREVEL_SMEM = 12480*4;
    const int NODE_SMEM   = 12416*4;
    const int EDGE_SMEM   = 17280*4;   // 69120 B
    cudaFuncSetAttribute(k_prevel, cudaFuncAttributeMaxDynamicSharedMemorySize, PREVEL_SMEM);
    cudaFuncSetAttribute(k_node,   cudaFuncAttributeMaxDynamicSharedMemorySize, NODE_SMEM);
    cudaFuncSetAttribute(k_edge,   cudaFuncAttributeMaxDynamicSharedMemorySize, EDGE_SMEM);

    k_init<<<(NN*H+255)/256, 256>>>(his, emb_w, emb_b, x, v);
    k_deg<<<(EE+255)/256, 256>>>(edges);
    k_scan<<<1, 1024>>>();
    k_fill<<<(EE+255)/256, 256>>>(edges, edge_attr);

    const int gn = 444;
    const int ge = 444;    // 148 SMs x 3 blocks; 24 autonomous warps/SM

    for (int l=0; l<3; l++){
        k_prevel<<<gn, 256, PREVEL_SMEM>>>(e_w1, e_b1, v_w1, v_b1, v_w2, v_b2);
        k_edge<<<ge, 256, EDGE_SMEM>>>(e_w1, e_w2, e_b2, c_w1, c_b1, c_w2);
        k_node<<<gn, 256, NODE_SMEM>>>(n_w1, n_b1, n_w2, n_b2,
                                       (float*)d_out, (l == 2) ? 1 : 0);
    }
}

// round 17
// speedup vs baseline: 1.0320x; 1.0320x over previous
#include <cuda_runtime.h>

#define NN 50000
#define EE 1600000
#define H  64
#define STEAL (EE/32)   // 50000 steal units of 32 edges (2 x 16-edge subtiles)

typedef unsigned long long ull;

// ---------------- scratch (device globals; no allocation allowed) ----------------
__device__ float g_h[NN*H];
__device__ float g_A[NN*H];      // h@Wa + e_b1
__device__ float g_B[NN*H];      // h@Wb
__device__ float g_magg[NN*H];   // segment-summed messages
__device__ float g_cagg4[NN*4];  // segment-summed coord updates (padded)
__device__ float g_vel[NN];      // vel_scale
__device__ float g_deg[NN];      // clipped out-degree (float)
__device__ int   g_cnt[NN];      // raw out-degree
__device__ int   g_off[NN];      // fill cursors
__device__ float g_x4[NN*4];     // padded coords
__device__ float g_v4[NN*4];     // padded velocities
__device__ int   g_tile;         // dynamic steal cursor
// r-sorted edge arrays
__device__ int    g_er[EE];
__device__ int    g_ec[EE];
__device__ float2 g_ea2[EE];

__device__ __forceinline__ float silu_f(float x){
    float th;
    asm("tanh.approx.f32 %0, %1;" : "=f"(th) : "f"(0.5f*x));
    return 0.5f*x*th + 0.5f*x;
}
__device__ __forceinline__ ull pack2(float x, float y){
    ull r; asm("mov.b64 %0, {%1,%2};" : "=l"(r) : "f"(x), "f"(y)); return r;
}
__device__ __forceinline__ float2 unpack2(ull p){
    float2 r; asm("mov.b64 {%0,%1}, %2;" : "=f"(r.x), "=f"(r.y) : "l"(p)); return r;
}
__device__ __forceinline__ void fma2(ull& d, ull a, ull b){
    asm("fma.rn.f32x2 %0, %1, %2, %0;" : "+l"(d) : "l"(a), "l"(b));
}
__device__ __forceinline__ void red4(float* p, float a, float b, float c, float d){
    asm volatile("red.global.add.v4.f32 [%0], {%1,%2,%3,%4};"
                 :: "l"(p), "f"(a), "f"(b), "f"(c), "f"(d) : "memory");
}
__device__ __forceinline__ void red2(float* p, float a, float b){
    asm volatile("red.global.add.v2.f32 [%0], {%1,%2};"
                 :: "l"(p), "f"(a), "f"(b) : "memory");
}
__device__ __forceinline__ unsigned to_tf32(float f){
    unsigned r; asm("cvt.rna.tf32.f32 %0, %1;" : "=r"(r) : "f"(f)); return r;
}
__device__ __forceinline__ void pf_l1(const float* p){
    asm volatile("prefetch.global.L1 [%0];" :: "l"(p));
}
// m16n8k8 tf32 MMA: D += A@B (A row-major 16x8, B col-major 8x8, fp32 accum)
__device__ __forceinline__ void mma8(float& d0, float& d1, float& d2, float& d3,
                                     unsigned a0, unsigned a1, unsigned a2, unsigned a3,
                                     ull b01){
    unsigned b0 = (unsigned)b01, b1 = (unsigned)(b01 >> 32);
    asm("mma.sync.aligned.m16n8k8.row.col.f32.tf32.tf32.f32 "
        "{%0,%1,%2,%3}, {%4,%5,%6,%7}, {%8,%9}, {%0,%1,%2,%3};"
        : "+f"(d0), "+f"(d1), "+f"(d2), "+f"(d3)
        : "r"(a0), "r"(a1), "r"(a2), "r"(a3), "r"(b0), "r"(b1));
}

// ---------------- init ------------------------------------------------------------
__global__ void k_init(const float* __restrict__ his, const float* __restrict__ emb_w,
                       const float* __restrict__ emb_b, const float* __restrict__ x,
                       const float* __restrict__ v){
    int idx = blockIdx.x*blockDim.x + threadIdx.x;
    if (idx < NN*H){
        int n = idx >> 6, j = idx & 63;
        float acc = emb_b[j];
        #pragma unroll
        for (int k=0;k<16;k++) acc += his[n*16+k]*emb_w[k*H+j];
        g_h[idx] = acc;
    }
    if (idx < NN){
        g_x4[idx*4+0]=x[idx*3+0]; g_x4[idx*4+1]=x[idx*3+1]; g_x4[idx*4+2]=x[idx*3+2]; g_x4[idx*4+3]=0.f;
        g_v4[idx*4+0]=v[idx*3+0]; g_v4[idx*4+1]=v[idx*3+1]; g_v4[idx*4+2]=v[idx*3+2]; g_v4[idx*4+3]=0.f;
        g_cnt[idx] = 0;
    }
}

__global__ void k_deg(const int* __restrict__ edges){
    int e = blockIdx.x*blockDim.x + threadIdx.x;
    if (e < EE) atomicAdd(&g_cnt[edges[e]], 1);
}

// single-block exclusive scan over g_cnt -> g_off; also g_deg = max(cnt,1)
__global__ void k_scan(){
    __shared__ int s_part[1024];
    int tid = threadIdx.x;
    const int CH = (NN + 1023)/1024;
    int base = tid*CH;
    int sum = 0;
    #pragma unroll 7
    for (int i=0;i<CH;i++){ int n=base+i; if(n<NN) sum += g_cnt[n]; }
    s_part[tid] = sum;
    __syncthreads();
    for (int off=1; off<1024; off<<=1){
        int t = (tid >= off) ? s_part[tid-off] : 0;
        __syncthreads();
        s_part[tid] += t;
        __syncthreads();
    }
    int run = s_part[tid] - sum;
    for (int i=0;i<CH;i++){
        int n = base+i;
        if (n < NN){
            int c = g_cnt[n];
            g_off[n] = run;
            g_deg[n] = (c > 0) ? (float)c : 1.0f;
            run += c;
        }
    }
}

__global__ void k_fill(const int* __restrict__ edges, const float* __restrict__ edge_attr){
    int e = blockIdx.x*blockDim.x + threadIdx.x;
    if (e < EE){
        int r = edges[e];
        int pos = atomicAdd(&g_off[r], 1);
        g_er[pos] = r;
        g_ec[pos] = edges[EE+e];
        g_ea2[pos] = ((const float2*)edge_attr)[e];
    }
}

// ------ per-layer node precompute (f32x2): A,B, vel_scale; zero aggs; reset cursor
__global__ void k_prevel(const float* __restrict__ e_w1, const float* __restrict__ e_b1,
                         const float* __restrict__ v_w1, const float* __restrict__ v_b1,
                         const float* __restrict__ v_w2, const float* __restrict__ v_b2){
    extern __shared__ float sp[];
    float* s_ew  = sp;
    float* s_vw  = sp + 8192;
    float* s_eb1 = sp + 12288;
    float* s_vb1 = sp + 12352;
    float* s_vw2 = sp + 12416;
    int tid = threadIdx.x;
    if (blockIdx.x == 0 && tid == 0) g_tile = 0;
    for (int i=tid; i<8192; i+=blockDim.x) s_ew[i] = e_w1[i];
    for (int i=tid; i<4096; i+=blockDim.x) s_vw[i] = v_w1[i];
    if (tid < 64){ s_eb1[tid]=e_b1[tid]; s_vb1[tid]=v_b1[tid]; s_vw2[tid]=v_w2[tid]; }
    __syncthreads();
    int lane = tid & 31, warp = tid >> 5;
    int j0 = 2*lane;
    int wpb = blockDim.x >> 5;
    float vb2 = v_b2[0];
    for (int n = blockIdx.x*wpb + warp; n < NN; n += gridDim.x*wpb){
        float h0 = g_h[n*H+j0], h1 = g_h[n*H+j0+1];
        ull a01 = *(const ull*)&s_eb1[j0];
        ull b01 = pack2(0.f, 0.f);
        ull t01 = *(const ull*)&s_vb1[j0];
        #pragma unroll
        for (int k=0;k<H;k++){
            float hk = __shfl_sync(0xffffffffu, (k&1)?h1:h0, k>>1);
            ull hk2 = pack2(hk, hk);
            fma2(a01, hk2, *(const ull*)&s_ew[k*H+j0]);
            fma2(b01, hk2, *(const ull*)&s_ew[(H+k)*H+j0]);
            fma2(t01, hk2, *(const ull*)&s_vw[k*H+j0]);
        }
        *(ull*)&g_A[n*H+j0] = a01;
        *(ull*)&g_B[n*H+j0] = b01;
        *(float2*)&g_magg[n*H+j0] = make_float2(0.f,0.f);
        float2 tv = unpack2(t01);
        float p = silu_f(tv.x)*s_vw2[j0] + silu_f(tv.y)*s_vw2[j0+1];
        #pragma unroll
        for (int o=16;o>0;o>>=1) p += __shfl_xor_sync(0xffffffffu, p, o);
        if (lane == 0){
            g_vel[n] = p + vb2;
            *(float4*)&g_cagg4[n*4] = make_float4(0.f,0.f,0.f,0.f);
        }
    }
}

// ------- edge kernel: 16-edge warp subtiles, tf32 mma, merged reds, prefetch ------
__global__ void __launch_bounds__(256, 3)
k_edge(const float* __restrict__ e_w1, const float* __restrict__ e_w2,
       const float* __restrict__ e_b2, const float* __restrict__ c_w1,
       const float* __restrict__ c_b1, const float* __restrict__ c_w2){
    extern __shared__ float sm[];
    ull*   w2p   = (ull*)sm;         // 2048 ull (packed tf32 B frags, GEMM1)
    ull*   c1p   = (ull*)(sm + 4096);// 2048 ull (GEMM2)
    float* s_wr  = sm + 8192;        // 64
    float* s_we0 = sm + 8256;
    float* s_we1 = sm + 8320;
    float* s_eb2 = sm + 8384;
    float* s_cb1 = sm + 8448;
    float* s_cw2 = sm + 8512;        // .. 8576
    int tid  = threadIdx.x;
    int wid  = tid >> 5, lane = tid & 31;
    float* wbp  = sm + 8576 + wid*1088;   // per-warp region (1088 floats)
    float* s_t  = wbp;                    // 64 x 16  (tf32 bits as float)
    int*   s_r  = (int*)(wbp + 1024);     // 16
    float* s_dx = wbp + 1040;             // 16
    float* s_dy = wbp + 1056;
    float* s_dz = wbp + 1072;
    // total smem: 8576 + 8*1088 = 17280 floats = 69120 B

    // pack weights into per-(ktile,ntile) lane-ordered tf32 B fragments
    for (int idx=tid; idx<2048; idx+=256){
        int tile = idx >> 5, vl = idx & 31;
        int kt = tile >> 3, nt = tile & 7;
        int tg = vl & 3,  gd = vl >> 2;
        int k0 = kt*8 + tg, j = nt*8 + gd;
        unsigned b0 = to_tf32(e_w2[k0*64 + j]);
        unsigned b1 = to_tf32(e_w2[(k0+4)*64 + j]);
        w2p[idx] = ((ull)b1 << 32) | (ull)b0;
        b0 = to_tf32(c_w1[k0*64 + j]);
        b1 = to_tf32(c_w1[(k0+4)*64 + j]);
        c1p[idx] = ((ull)b1 << 32) | (ull)b0;
    }
    if (tid < 64){
        s_wr [tid] = e_w1[128*H+tid];
        s_we0[tid] = e_w1[129*H+tid];
        s_we1[tid] = e_w1[130*H+tid];
        s_eb2[tid] = e_b2[tid];
        s_cb1[tid] = c_b1[tid];
        s_cw2[tid] = c_w2[tid];
    }
    __syncthreads();

    const unsigned FM = 0xffffffffu;
    int el = lane & 15, hf = lane >> 4;   // P1: 2 lanes/edge
    int tig = lane & 3, gid = lane >> 2;  // mma fragment coords

    int base = 0;
    if (lane == 0) base = atomicAdd(&g_tile, 1);
    base = __shfl_sync(FM, base, 0);

    while (base < STEAL){
        #pragma unroll 1
        for (int sub=0; sub<2; sub++){
            // ---- P1: gather + first-layer pre + silu -> tf32 s_t[k][e] ----
            {
                int e = base*32 + sub*16 + el;
                int r = g_er[e], c = g_ec[e];
                if (sub == 0){
                    int e2 = e + 16;
                    int rn = g_er[e2], cn = g_ec[e2];
                    pf_l1(g_A + rn*H + hf*32);
                    pf_l1(g_B + cn*H + hf*32);
                }
                float4 xr = *(const float4*)&g_x4[r*4];
                float4 xc = *(const float4*)&g_x4[c*4];
                float dx = xr.x-xc.x, dy = xr.y-xc.y, dz = xr.z-xc.z;
                float radial = dx*dx + dy*dy + dz*dz;
                float2 ea = g_ea2[e];
                const float4* Ap = (const float4*)(g_A + r*H + hf*32);
                const float4* Bp = (const float4*)(g_B + c*H + hf*32);
                int kb = hf*32;
                #pragma unroll
                for (int q=0;q<8;q++){
                    float4 av = Ap[q], bv = Bp[q];
                    int k = kb + 4*q;
                    float4 w1 = *(const float4*)&s_wr [k];
                    float4 w2 = *(const float4*)&s_we0[k];
                    float4 w3 = *(const float4*)&s_we1[k];
                    s_t[(k+0)*16+el] = __uint_as_float(to_tf32(
                        silu_f(av.x + bv.x + radial*w1.x + ea.x*w2.x + ea.y*w3.x)));
                    s_t[(k+1)*16+el] = __uint_as_float(to_tf32(
                        silu_f(av.y + bv.y + radial*w1.y + ea.x*w2.y + ea.y*w3.y)));
                    s_t[(k+2)*16+el] = __uint_as_float(to_tf32(
                        silu_f(av.z + bv.z + radial*w1.z + ea.x*w2.z + ea.y*w3.z)));
                    s_t[(k+3)*16+el] = __uint_as_float(to_tf32(
                        silu_f(av.w + bv.w + radial*w1.w + ea.x*w2.w + ea.y*w3.w)));
                }
                if (!hf){ s_r[el]=r; s_dx[el]=dx; s_dy[el]=dy; s_dz[el]=dz; }
            }
            __syncwarp();

            // ---- load A fragments for GEMM1 (t, all 8 k-tiles) ----
            unsigned af[32];
            #pragma unroll
            for (int kt=0;kt<8;kt++){
                const float* b = s_t + (kt*8 + tig)*16 + gid;
                af[kt*4+0] = __float_as_uint(b[0]);
                af[kt*4+1] = __float_as_uint(b[8]);
                af[kt*4+2] = __float_as_uint(b[64]);
                af[kt*4+3] = __float_as_uint(b[72]);
            }
            __syncwarp();

            int r0 = s_r[gid], r1 = s_r[gid+8];
            int rsame = (r0 == r1);

            // ---- GEMM1 (8 n-tiles): M = t @ e_w2 + b; silu; merged scatter -------
            #pragma unroll
            for (int nt=0;nt<8;nt++){
                int c0 = nt*8 + 2*tig;
                float d0 = s_eb2[c0], d1 = s_eb2[c0+1];
                float d2 = d0, d3 = d1;
                #pragma unroll
                for (int kt=0;kt<8;kt++)
                    mma8(d0,d1,d2,d3, af[kt*4],af[kt*4+1],af[kt*4+2],af[kt*4+3],
                         w2p[(kt*8+nt)*32 + lane]);
                float m0 = silu_f(d0), m1 = silu_f(d1);
                float m2 = silu_f(d2), m3 = silu_f(d3);
                if (rsame){
                    red2(&g_magg[r0*H + c0], m0+m2, m1+m3);
                } else {
                    red2(&g_magg[r0*H + c0], m0, m1);
                    red2(&g_magg[r1*H + c0], m2, m3);
                }
                s_t[ c0   *16 + gid  ] = __uint_as_float(to_tf32(m0));
                s_t[(c0+1)*16 + gid  ] = __uint_as_float(to_tf32(m1));
                s_t[ c0   *16 + gid+8] = __uint_as_float(to_tf32(m2));
                s_t[(c0+1)*16 + gid+8] = __uint_as_float(to_tf32(m3));
            }
            __syncwarp();

            // ---- load A fragments for GEMM2 (m) ----
            #pragma unroll
            for (int kt=0;kt<8;kt++){
                const float* b = s_t + (kt*8 + tig)*16 + gid;
                af[kt*4+0] = __float_as_uint(b[0]);
                af[kt*4+1] = __float_as_uint(b[8]);
                af[kt*4+2] = __float_as_uint(b[64]);
                af[kt*4+3] = __float_as_uint(b[72]);
            }
            __syncwarp();

            // ---- GEMM2: U = m @ c_w1 + cb1; g = sum silu(U)*cw2 ----
            float gp0 = 0.f, gp1 = 0.f;
            #pragma unroll
            for (int nt=0;nt<8;nt++){
                int c0 = nt*8 + 2*tig;
                float d0 = s_cb1[c0], d1 = s_cb1[c0+1];
                float d2 = d0, d3 = d1;
                #pragma unroll
                for (int kt=0;kt<8;kt++)
                    mma8(d0,d1,d2,d3, af[kt*4],af[kt*4+1],af[kt*4+2],af[kt*4+3],
                         c1p[(kt*8+nt)*32 + lane]);
                float w0 = s_cw2[c0], w1 = s_cw2[c0+1];
                gp0 += silu_f(d0)*w0 + silu_f(d1)*w1;
                gp1 += silu_f(d2)*w0 + silu_f(d3)*w1;
            }
            gp0 += __shfl_xor_sync(FM, gp0, 1);
            gp0 += __shfl_xor_sync(FM, gp0, 2);
            gp1 += __shfl_xor_sync(FM, gp1, 1);
            gp1 += __shfl_xor_sync(FM, gp1, 2);
            if (tig == 0){
                float cx0 = s_dx[gid]*gp0,   cy0 = s_dy[gid]*gp0,   cz0 = s_dz[gid]*gp0;
                float cx1 = s_dx[gid+8]*gp1, cy1 = s_dy[gid+8]*gp1, cz1 = s_dz[gid+8]*gp1;
                if (rsame){
                    red4(&g_cagg4[r0*4], cx0+cx1, cy0+cy1, cz0+cz1, 0.f);
                } else {
                    red4(&g_cagg4[r0*4], cx0, cy0, cz0, 0.f);
                    red4(&g_cagg4[r1*4], cx1, cy1, cz1, 0.f);
                }
            }
            __syncwarp();   // protect s_t/s_r before next subtile's P1
        }
        if (lane == 0) base = atomicAdd(&g_tile, 1);
        base = __shfl_sync(FM, base, 0);
    }
}

// -------- fused node MLP + state update (f32x2); last layer writes output ---------
__global__ void k_node(const float* __restrict__ n_w1, const float* __restrict__ n_b1,
                       const float* __restrict__ n_w2, const float* __restrict__ n_b2,
                       float* __restrict__ out, int last){
    extern __shared__ float sn[];
    float* s_w1 = sn;
    float* s_w2 = sn + 8192;
    float* s_b1 = sn + 12288;
    float* s_b2 = sn + 12352;
    int tid = threadIdx.x;
    for (int i=tid; i<8192; i+=blockDim.x) s_w1[i] = n_w1[i];
    for (int i=tid; i<4096; i+=blockDim.x) s_w2[i] = n_w2[i];
    if (tid < 64){ s_b1[tid]=n_b1[tid]; s_b2[tid]=n_b2[tid]; }
    __syncthreads();
    int lane = tid & 31, warp = tid >> 5;
    int j0 = 2*lane;
    int wpb = blockDim.x >> 5;
    for (int n = blockIdx.x*wpb + warp; n < NN; n += gridDim.x*wpb){
        float h0 = g_h[n*H+j0],    h1 = g_h[n*H+j0+1];
        float m0 = g_magg[n*H+j0], m1 = g_magg[n*H+j0+1];
        ull u01 = *(const ull*)&s_b1[j0];
        #pragma unroll
        for (int k=0;k<H;k++){
            float hk = __shfl_sync(0xffffffffu, (k&1)?h1:h0, k>>1);
            float mk = __shfl_sync(0xffffffffu, (k&1)?m1:m0, k>>1);
            fma2(u01, pack2(hk,hk), *(const ull*)&s_w1[k*H+j0]);
            fma2(u01, pack2(mk,mk), *(const ull*)&s_w1[(H+k)*H+j0]);
        }
        float2 uv = unpack2(u01);
        float u0 = silu_f(uv.x), u1 = silu_f(uv.y);
        ull a01 = *(const ull*)&s_b2[j0];
        #pragma unroll
        for (int k=0;k<H;k++){
            float uk = __shfl_sync(0xffffffffu, (k&1)?u1:u0, k>>1);
            fma2(a01, pack2(uk,uk), *(const ull*)&s_w2[k*H+j0]);
        }
        float2 av = unpack2(a01);
        float hn0 = 2.f*h0 + av.x, hn1 = 2.f*h1 + av.y;
        *(float2*)&g_h[n*H+j0] = make_float2(hn0, hn1);
        float vn = 0.f, xn = 0.f;
        if (lane < 3){
            float dg = g_deg[n];
            float cm = g_cagg4[n*4+lane] / dg;
            float vi = g_v4[n*4+lane];
            vn = vi + cm + g_vel[n]*vi;
            g_v4[n*4+lane] = vn;
            xn = g_x4[n*4+lane] + vn;
            g_x4[n*4+lane] = xn;
        }
        if (last){
            *(float2*)&out[NN*3 + n*H + j0] = make_float2(hn0, hn1);
            if (lane < 3){
                out[n*3 + lane] = xn;
                out[NN*3 + NN*H + n*3 + lane] = vn;
            }
        }
    }
}

extern "C" void kernel_launch(void* const* d_in, const int* in_sizes, int n_in,
                              void* d_out, int out_size){
    const float* his  = (const float*)d_in[0];
    const float* x    = (const float*)d_in[1];
    const float* v    = (const float*)d_in[2];
    const float* edge_attr = (const float*)d_in[3];
    const int*   edges= (const int*)  d_in[4];
    const float* emb_w= (const float*)d_in[5];
    const float* emb_b= (const float*)d_in[6];
    const float* e_w1 = (const float*)d_in[7];
    const float* e_b1 = (const float*)d_in[8];
    const float* e_w2 = (const float*)d_in[9];
    const float* e_b2 = (const float*)d_in[10];
    const float* c_w1 = (const float*)d_in[11];
    const float* c_b1 = (const float*)d_in[12];
    const float* c_w2 = (const float*)d_in[13];
    const float* n_w1 = (const float*)d_in[14];
    const float* n_b1 = (const float*)d_in[15];
    const float* n_w2 = (const float*)d_in[16];
    const float* n_b2 = (const float*)d_in[17];
    const float* v_w1 = (const float*)d_in[18];
    const float* v_b1 = (const float*)d_in[19];
    const float* v_w2 = (const float*)d_in[20];
    const float* v_b2 = (const float*)d_in[21];

    const int PREVEL_SMEM = 12480*4;
    const int NODE_SMEM   = 12416*4;
    const int EDGE_SMEM   = 17280*4;   // 69120 B
    cudaFuncSetAttribute(k_prevel, cudaFuncAttributeMaxDynamicSharedMemorySize, PREVEL_SMEM);
    cudaFuncSetAttribute(k_node,   cudaFuncAttributeMaxDynamicSharedMemorySize, NODE_SMEM);
    cudaFuncSetAttribute(k_edge,   cudaFuncAttributeMaxDynamicSharedMemorySize, EDGE_SMEM);

    k_init<<<(NN*H+255)/256, 256>>>(his, emb_w, emb_b, x, v);
    k_deg<<<(EE+255)/256, 256>>>(edges);
    k_scan<<<1, 1024>>>();
    k_fill<<<(EE+255)/256, 256>>>(edges, edge_attr);

    const int gn = 444;
    const int ge = 444;    // 148 SMs x 3 blocks; 24 autonomous warps/SM

    for (int l=0; l<3; l++){
        k_prevel<<<gn, 256, PREVEL_SMEM>>>(e_w1, e_b1, v_w1, v_b1, v_w2, v_b2);
        k_edge<<<ge, 256, EDGE_SMEM>>>(e_w1, e_w2, e_b2, c_w1, c_b1, c_w2);
        k_node<<<gn, 256, NODE_SMEM>>>(n_w1, n_b1, n_w2, n_b2,
                                       (float*)d_out, (l == 2) ? 1 : 0);
    }
}